// round 6
// baseline (speedup 1.0000x reference)
#include <cuda_runtime.h>
#include <cuda_fp16.h>
#include <cstdint>

// ---------------------------------------------------------------------------
//   h  [B, N, C]  B=4, N=256, C=512;  e [B, N, N, C];  W* [C, 512]
// Outputs packed in d_out: h_out [B,N,512] then e_out [B,N,N,512]
// ---------------------------------------------------------------------------
#define Bb   4
#define Nn   256
#define Cc   512
#define Hh   8
#define HD   512
#define ME_ROWS  (Bb*Nn*Nn)
#define HOUT_ELEMS (Bb*Nn*HD)

__device__ float g_Q[Bb*Nn*HD];
__device__ float g_K[Bb*Nn*HD];
__device__ float g_V[Bb*Nn*HD];
__device__ float g_s[Bb*Nn*Nn*Hh];
__device__ float g_w[Bb*Nn*Nn*Hh];
__device__ __half g_WeT_h[HD*Cc];   // [n][k] = fp16(We[k][n])

// ===========================================================================
__device__ __forceinline__ uint32_t smem_u32(const void* p) {
    uint32_t a;
    asm("{ .reg .u64 t; cvta.to.shared.u64 t, %1; cvt.u32.u64 %0, t; }" : "=r"(a) : "l"(p));
    return a;
}
__device__ __forceinline__ void cp_async16(uint32_t dst, const void* src) {
    asm volatile("cp.async.cg.shared.global [%0], [%1], 16;" :: "r"(dst), "l"(src));
}
#define CP_COMMIT() asm volatile("cp.async.commit_group;" ::: "memory")
#define CP_WAIT0()  asm volatile("cp.async.wait_group 0;" ::: "memory")

__device__ __forceinline__ void ldsm_x4(uint32_t addr, uint32_t& r0, uint32_t& r1,
                                        uint32_t& r2, uint32_t& r3) {
    asm volatile("ldmatrix.sync.aligned.m8n8.x4.shared.b16 {%0,%1,%2,%3}, [%4];"
        : "=r"(r0), "=r"(r1), "=r"(r2), "=r"(r3) : "r"(addr));
}
__device__ __forceinline__ void mma_f16(float* d, const uint32_t* a,
                                        uint32_t b0, uint32_t b1) {
    asm volatile("mma.sync.aligned.m16n8k16.row.col.f32.f16.f16.f32 "
        "{%0,%1,%2,%3}, {%4,%5,%6,%7}, {%8,%9}, {%0,%1,%2,%3};"
        : "+f"(d[0]), "+f"(d[1]), "+f"(d[2]), "+f"(d[3])
        : "r"(a[0]), "r"(a[1]), "r"(a[2]), "r"(a[3]), "r"(b0), "r"(b1));
}
__device__ __forceinline__ uint32_t pack_h2(float a, float b) {
    __half2 h = __floats2half2_rn(a, b);
    return *reinterpret_cast<uint32_t*>(&h);
}

// ===========================================================================
// K0: We -> WeT fp16 (transposed)
// ===========================================================================
__global__ void prep_we_kernel(const float* __restrict__ We) {
    const int n = blockIdx.x;
    const int k = threadIdx.x;
    g_WeT_h[(size_t)n * Cc + k] = __float2half_rn(We[(size_t)k * HD + n]);
}

// ===========================================================================
// K1: QKV projection — 64x64 tiles, 384 CTAs (fp32 exact)
// ===========================================================================
#define QBM 64
#define QBN 64
#define QBK 8
#define QPAD 68
__global__ void qkv_kernel(const float* __restrict__ h,
                           const float* __restrict__ Wq,
                           const float* __restrict__ Wk,
                           const float* __restrict__ Wv)
{
    __shared__ float As[QBK][QPAD];
    __shared__ float Bs[QBK][QPAD];
    const int z = blockIdx.z;
    const float* W = (z == 0) ? Wq : (z == 1) ? Wk : Wv;
    float* O = (z == 0) ? g_Q : (z == 1) ? g_K : g_V;

    const int row0 = blockIdx.y * QBM;
    const int col0 = blockIdx.x * QBN;
    const int tid  = threadIdx.x;

    const int ar = tid >> 2;              // 0..63
    const int ak = (tid & 3) * 2;         // 0,2,4,6
    const int br = tid >> 5;              // 0..7
    const int bc = (tid & 31) * 2;        // 0..62
    const int tx = tid & 15;
    const int ty = tid >> 4;

    float acc[4][4] = {};
    const float* Ap = h + (size_t)(row0 + ar) * Cc + ak;
    const float* Bp = W + (size_t)br * HD + col0 + bc;

    for (int k0 = 0; k0 < Cc; k0 += QBK) {
        float2 av = *reinterpret_cast<const float2*>(Ap + k0);
        As[ak][ar] = av.x;
        As[ak + 1][ar] = av.y;
        float2 bv = *reinterpret_cast<const float2*>(Bp + (size_t)k0 * HD);
        Bs[br][bc] = bv.x;
        Bs[br][bc + 1] = bv.y;
        __syncthreads();
        #pragma unroll
        for (int k = 0; k < QBK; ++k) {
            float a[4], b[4];
            float4 a0 = *reinterpret_cast<const float4*>(&As[k][ty * 4]);
            a[0]=a0.x; a[1]=a0.y; a[2]=a0.z; a[3]=a0.w;
            float4 b0 = *reinterpret_cast<const float4*>(&Bs[k][tx * 4]);
            b[0]=b0.x; b[1]=b0.y; b[2]=b0.z; b[3]=b0.w;
            #pragma unroll
            for (int i = 0; i < 4; ++i)
                #pragma unroll
                for (int j = 0; j < 4; ++j)
                    acc[i][j] += a[i] * b[j];
        }
        __syncthreads();
    }
    #pragma unroll
    for (int i = 0; i < 4; ++i) {
        size_t m = (size_t)(row0 + ty * 4 + i);
        *reinterpret_cast<float4*>(O + m * HD + col0 + tx * 4) =
            make_float4(acc[i][0], acc[i][1], acc[i][2], acc[i][3]);
    }
}

// ===========================================================================
// K2: fp16 HMMA GEMM (e @ We) + fused Q*K/8 epilogue + per-head rowsums
//     CTA: 128 rows x 256 cols, K=512 in 8 chunks of 64.  512 threads.
// ===========================================================================
#define KC 64
#define NCHUNK 8
#define RSTRIDE 144              // 128B data + 16B pad (conflict-free ldmatrix)
#define A_OFF 0                  // 128 x 144 = 18432
#define B_OFF 18432              // 256 x 144 = 36864
#define BUF_STRIDE 55296
#define SMEM_PE (2*BUF_STRIDE)   // 110592 B

__global__ void __launch_bounds__(512, 1) pe_mma_kernel(
    const float* __restrict__ e, float* __restrict__ eout)
{
    extern __shared__ char smem[];
    const uint32_t sb = smem_u32(smem);
    const int tid  = threadIdx.x;
    const int lane = tid & 31;
    const int w    = tid >> 5;        // 0..15
    const int wm   = w & 3;
    const int wn   = w >> 2;
    const int n0   = blockIdx.x;      // 0..1 (256-col half)
    const int m0   = blockIdx.y * 128;

    // A staging: row = tid>>2 (0..127), quarter = tid&3 (16 floats each)
    const int arow = tid >> 2;
    const int aq   = tid & 3;
    const uint32_t a_sts = (uint32_t)(arow * RSTRIDE + aq * 32);
    const float* eA = e + (size_t)(m0 + arow) * Cc + aq * 16;

    // B staging: row = tid>>1 (0..255), half = tid&1 (32 fp16 = 64B each)
    const int brow = tid >> 1;
    const int bh   = tid & 1;
    const uint32_t b_sts = (uint32_t)(brow * RSTRIDE + bh * 64);
    const __half* WhA = g_WeT_h + (size_t)(n0 * 256 + brow) * Cc + bh * 32;

    float acc[2][8][4];
    #pragma unroll
    for (int mt = 0; mt < 2; ++mt)
        #pragma unroll
        for (int nt = 0; nt < 8; ++nt)
            #pragma unroll
            for (int i = 0; i < 4; ++i) acc[mt][nt][i] = 0.f;

    float4 a_reg[4];

    // ---- prologue: stage chunk 0 into buf 0 ----
    {
        cp_async16(sb + B_OFF + b_sts +  0, WhA);
        cp_async16(sb + B_OFF + b_sts + 16, WhA + 8);
        cp_async16(sb + B_OFF + b_sts + 32, WhA + 16);
        cp_async16(sb + B_OFF + b_sts + 48, WhA + 24);
        CP_COMMIT();
        #pragma unroll
        for (int i = 0; i < 4; ++i)
            a_reg[i] = *reinterpret_cast<const float4*>(eA + i * 4);
        uint4 hv;
        hv.x = pack_h2(a_reg[0].x, a_reg[0].y);
        hv.y = pack_h2(a_reg[0].z, a_reg[0].w);
        hv.z = pack_h2(a_reg[1].x, a_reg[1].y);
        hv.w = pack_h2(a_reg[1].z, a_reg[1].w);
        *reinterpret_cast<uint4*>(smem + A_OFF + a_sts) = hv;
        hv.x = pack_h2(a_reg[2].x, a_reg[2].y);
        hv.y = pack_h2(a_reg[2].z, a_reg[2].w);
        hv.z = pack_h2(a_reg[3].x, a_reg[3].y);
        hv.w = pack_h2(a_reg[3].z, a_reg[3].w);
        *reinterpret_cast<uint4*>(smem + A_OFF + a_sts + 16) = hv;
        CP_WAIT0();
        __syncthreads();
    }

    // ---- main loop ----
    for (int s = 0; s < NCHUNK; ++s) {
        const uint32_t buf = (uint32_t)(s & 1) * BUF_STRIDE;
        const uint32_t nb  = (uint32_t)((s + 1) & 1) * BUF_STRIDE;
        const bool more = (s + 1 < NCHUNK);

        if (more) {
            const int k0 = (s + 1) * KC;
            cp_async16(sb + nb + B_OFF + b_sts +  0, WhA + k0);
            cp_async16(sb + nb + B_OFF + b_sts + 16, WhA + k0 + 8);
            cp_async16(sb + nb + B_OFF + b_sts + 32, WhA + k0 + 16);
            cp_async16(sb + nb + B_OFF + b_sts + 48, WhA + k0 + 24);
            CP_COMMIT();
            #pragma unroll
            for (int i = 0; i < 4; ++i)
                a_reg[i] = *reinterpret_cast<const float4*>(eA + k0 + i * 4);
        }

        // compute chunk s (4 k16 steps)
        #pragma unroll
        for (int kk = 0; kk < 4; ++kk) {
            const uint32_t kb = (uint32_t)(kk * 32 + (lane >> 4) * 16);
            uint32_t af[2][4];
            #pragma unroll
            for (int mt = 0; mt < 2; ++mt) {
                const uint32_t ra = sb + buf + A_OFF +
                    (uint32_t)((wm*32 + mt*16 + (lane & 15)) * RSTRIDE) + kb;
                ldsm_x4(ra, af[mt][0], af[mt][1], af[mt][2], af[mt][3]);
            }
            uint32_t bf[4][4];
            #pragma unroll
            for (int g = 0; g < 4; ++g) {
                const uint32_t rb = sb + buf + B_OFF +
                    (uint32_t)((wn*64 + g*16 + (lane & 15)) * RSTRIDE) + kb;
                ldsm_x4(rb, bf[g][0], bf[g][1], bf[g][2], bf[g][3]);
            }
            #pragma unroll
            for (int mt = 0; mt < 2; ++mt)
                #pragma unroll
                for (int nt = 0; nt < 8; ++nt) {
                    const int g = nt >> 1, o = nt & 1;
                    mma_f16(acc[mt][nt], af[mt], bf[g][o], bf[g][o+2]);
                }
        }

        if (more) {
            uint4 hv;
            hv.x = pack_h2(a_reg[0].x, a_reg[0].y);
            hv.y = pack_h2(a_reg[0].z, a_reg[0].w);
            hv.z = pack_h2(a_reg[1].x, a_reg[1].y);
            hv.w = pack_h2(a_reg[1].z, a_reg[1].w);
            *reinterpret_cast<uint4*>(smem + nb + A_OFF + a_sts) = hv;
            hv.x = pack_h2(a_reg[2].x, a_reg[2].y);
            hv.y = pack_h2(a_reg[2].z, a_reg[2].w);
            hv.z = pack_h2(a_reg[3].x, a_reg[3].y);
            hv.w = pack_h2(a_reg[3].z, a_reg[3].w);
            *reinterpret_cast<uint4*>(smem + nb + A_OFF + a_sts + 16) = hv;
            CP_WAIT0();
        }
        __syncthreads();
    }

    // ---- epilogue: v = acc * (Q*0.125) * K -> e_out; per-head rowsum -> g_s
    const int q  = lane & 3;
    const int rr = lane >> 2;
    const int bi = blockIdx.y >> 1;             // b*N + i
    const int b  = bi >> 8;
    const int jbase = (blockIdx.y & 1) * 128;
    const int cb = n0 * 256 + wn * 64;
    const int head = cb >> 6;

    float2 qv[8];
    #pragma unroll
    for (int nt = 0; nt < 8; ++nt) {
        float2 t = *reinterpret_cast<const float2*>(
            g_Q + (size_t)bi * HD + cb + nt*8 + 2*q);
        qv[nt] = make_float2(t.x * 0.125f, t.y * 0.125f);
    }

    #pragma unroll
    for (int mt = 0; mt < 2; ++mt)
        #pragma unroll
        for (int half = 0; half < 2; ++half) {
            const int r = wm*32 + mt*16 + rr + half*8;
            const size_t m = (size_t)m0 + r;
            const int j = jbase + r;
            const float* kp = g_K + ((size_t)(b * Nn + j)) * HD + cb + 2*q;
            float* op = eout + m * HD + cb + 2*q;
            float hs = 0.f;
            #pragma unroll
            for (int nt = 0; nt < 8; ++nt) {
                float2 kv = *reinterpret_cast<const float2*>(kp + nt*8);
                float v0 = acc[mt][nt][half*2+0] * qv[nt].x * kv.x;
                float v1 = acc[mt][nt][half*2+1] * qv[nt].y * kv.y;
                *reinterpret_cast<float2*>(op + nt*8) = make_float2(v0, v1);
                hs += v0 + v1;
            }
            hs += __shfl_xor_sync(0xffffffffu, hs, 1);
            hs += __shfl_xor_sync(0xffffffffu, hs, 2);
            if (q == 0)
                g_s[m * Hh + head] = fminf(fmaxf(hs, -5.f), 5.f);
        }
}

// ===========================================================================
// K4: softmax over key axis j — one block per (b, i), all 8 heads
// ===========================================================================
__global__ void softmax_kernel()
{
    const int bi = blockIdx.x;       // 0 .. B*N-1
    const int j  = threadIdx.x;      // 0..255

    __shared__ float red[Hh][Nn];

    const float* sp = g_s + ((size_t)bi * Nn + j) * Hh;
    float4 v0 = *reinterpret_cast<const float4*>(sp);
    float4 v1 = *reinterpret_cast<const float4*>(sp + 4);
    float ev[8];
    ev[0] = __expf(v0.x); ev[1] = __expf(v0.y);
    ev[2] = __expf(v0.z); ev[3] = __expf(v0.w);
    ev[4] = __expf(v1.x); ev[5] = __expf(v1.y);
    ev[6] = __expf(v1.z); ev[7] = __expf(v1.w);
    #pragma unroll
    for (int hh = 0; hh < 8; ++hh) red[hh][j] = ev[hh];
    __syncthreads();

    #pragma unroll
    for (int lg = 7; lg >= 0; --lg) {
        const int st = 1 << lg;
        for (int idx = threadIdx.x; idx < 8 * st; idx += Nn) {
            const int hh = idx >> lg;
            const int jj = idx & (st - 1);
            red[hh][jj] += red[hh][jj + st];
        }
        __syncthreads();
    }

    float* wp = g_w + ((size_t)bi * Nn + j) * Hh;
    float o[8];
    #pragma unroll
    for (int hh = 0; hh < 8; ++hh) o[hh] = __fdividef(ev[hh], red[hh][0]);
    *reinterpret_cast<float4*>(wp)     = make_float4(o[0], o[1], o[2], o[3]);
    *reinterpret_cast<float4*>(wp + 4) = make_float4(o[4], o[5], o[6], o[7]);
}

// ===========================================================================
// K5: h_out = softmax weights @ V
// ===========================================================================
__global__ void attn_out_kernel(float* __restrict__ hout)
{
    const int bi = blockIdx.x;
    const int c  = threadIdx.x;
    const int hh = c >> 6;

    __shared__ float ws[Nn * Hh];
    for (int idx = threadIdx.x; idx < Nn * Hh; idx += blockDim.x)
        ws[idx] = g_w[(size_t)bi * Nn * Hh + idx];
    __syncthreads();

    const int b = bi >> 8;
    const float* vb = g_V + (size_t)(b * Nn) * HD + c;
    float a0 = 0.f, a1 = 0.f, a2 = 0.f, a3 = 0.f;
    #pragma unroll 4
    for (int j = 0; j < Nn; j += 4) {
        a0 = fmaf(ws[(j+0) * Hh + hh], vb[(size_t)(j+0) * HD], a0);
        a1 = fmaf(ws[(j+1) * Hh + hh], vb[(size_t)(j+1) * HD], a1);
        a2 = fmaf(ws[(j+2) * Hh + hh], vb[(size_t)(j+2) * HD], a2);
        a3 = fmaf(ws[(j+3) * Hh + hh], vb[(size_t)(j+3) * HD], a3);
    }
    hout[(size_t)bi * HD + c] = (a0 + a1) + (a2 + a3);
}

// ===========================================================================
extern "C" void kernel_launch(void* const* d_in, const int* in_sizes, int n_in,
                              void* d_out, int out_size)
{
    const float* h  = (const float*)d_in[0];
    const float* e  = (const float*)d_in[1];
    const float* Wq = (const float*)d_in[2];
    const float* Wk = (const float*)d_in[3];
    const float* Wv = (const float*)d_in[4];
    const float* We = (const float*)d_in[5];

    float* out  = (float*)d_out;
    float* hout = out;
    float* eout = out + HOUT_ELEMS;

    cudaFuncSetAttribute(pe_mma_kernel,
                         cudaFuncAttributeMaxDynamicSharedMemorySize, SMEM_PE);

    prep_we_kernel<<<HD, Cc>>>(We);
    {
        dim3 grid(HD / QBN, (Bb * Nn) / QBM, 3);
        qkv_kernel<<<grid, 256>>>(h, Wq, Wk, Wv);
    }
    {
        dim3 grid(2, ME_ROWS / 128);
        pe_mma_kernel<<<grid, 512, SMEM_PE>>>(e, eout);
    }
    softmax_kernel<<<Bb * Nn, Nn>>>();
    attn_out_kernel<<<Bb * Nn, HD>>>(hout);
}

// round 8
// speedup vs baseline: 1.1354x; 1.1354x over previous
#include <cuda_runtime.h>
#include <cuda_fp16.h>
#include <cstdint>

// ---------------------------------------------------------------------------
//   h  [B, N, C]  B=4, N=256, C=512;  e [B, N, N, C];  W* [C, 512]
// Outputs packed in d_out: h_out [B,N,512] then e_out [B,N,N,512]
// ---------------------------------------------------------------------------
#define Bb   4
#define Nn   256
#define Cc   512
#define Hh   8
#define HD   512
#define ME_ROWS  (Bb*Nn*Nn)
#define HOUT_ELEMS (Bb*Nn*HD)

__device__ float g_Q[Bb*Nn*HD];
__device__ float g_K[Bb*Nn*HD];
__device__ float g_V[Bb*Nn*HD];
__device__ float g_s[Bb*Nn*Nn*Hh];
__device__ float g_w[Bb*Nn*Nn*Hh];
__device__ __half g_WeT_h[HD*Cc];   // [n][k] = fp16(We[k][n])

// ===========================================================================
__device__ __forceinline__ uint32_t smem_u32(const void* p) {
    uint32_t a;
    asm("{ .reg .u64 t; cvta.to.shared.u64 t, %1; cvt.u32.u64 %0, t; }" : "=r"(a) : "l"(p));
    return a;
}
__device__ __forceinline__ void cp_async16(uint32_t dst, const void* src) {
    asm volatile("cp.async.cg.shared.global [%0], [%1], 16;" :: "r"(dst), "l"(src));
}
#define CP_COMMIT() asm volatile("cp.async.commit_group;" ::: "memory")
#define CP_WAIT0()  asm volatile("cp.async.wait_group 0;" ::: "memory")

__device__ __forceinline__ void ldsm_x4(uint32_t addr, uint32_t& r0, uint32_t& r1,
                                        uint32_t& r2, uint32_t& r3) {
    asm volatile("ldmatrix.sync.aligned.m8n8.x4.shared.b16 {%0,%1,%2,%3}, [%4];"
        : "=r"(r0), "=r"(r1), "=r"(r2), "=r"(r3) : "r"(addr));
}
__device__ __forceinline__ void mma_f16(float* d, const uint32_t* a,
                                        uint32_t b0, uint32_t b1) {
    asm volatile("mma.sync.aligned.m16n8k16.row.col.f32.f16.f16.f32 "
        "{%0,%1,%2,%3}, {%4,%5,%6,%7}, {%8,%9}, {%0,%1,%2,%3};"
        : "+f"(d[0]), "+f"(d[1]), "+f"(d[2]), "+f"(d[3])
        : "r"(a[0]), "r"(a[1]), "r"(a[2]), "r"(a[3]), "r"(b0), "r"(b1));
}
__device__ __forceinline__ uint32_t pack_h2(float a, float b) {
    __half2 h = __floats2half2_rn(a, b);
    return *reinterpret_cast<uint32_t*>(&h);
}

// ===========================================================================
// K0: We -> WeT fp16 (transposed)
// ===========================================================================
__global__ void prep_we_kernel(const float* __restrict__ We) {
    const int n = blockIdx.x;
    const int k = threadIdx.x;
    g_WeT_h[(size_t)n * Cc + k] = __float2half_rn(We[(size_t)k * HD + n]);
}

// ===========================================================================
// K1: QKV projection — 64x64 tiles, 384 CTAs (fp32 exact)
// ===========================================================================
#define QBM 64
#define QBN 64
#define QBK 8
#define QPAD 68
__global__ void qkv_kernel(const float* __restrict__ h,
                           const float* __restrict__ Wq,
                           const float* __restrict__ Wk,
                           const float* __restrict__ Wv)
{
    __shared__ float As[QBK][QPAD];
    __shared__ float Bs[QBK][QPAD];
    const int z = blockIdx.z;
    const float* W = (z == 0) ? Wq : (z == 1) ? Wk : Wv;
    float* O = (z == 0) ? g_Q : (z == 1) ? g_K : g_V;

    const int row0 = blockIdx.y * QBM;
    const int col0 = blockIdx.x * QBN;
    const int tid  = threadIdx.x;

    const int ar = tid >> 2;              // 0..63
    const int ak = (tid & 3) * 2;         // 0,2,4,6
    const int br = tid >> 5;              // 0..7
    const int bc = (tid & 31) * 2;        // 0..62
    const int tx = tid & 15;
    const int ty = tid >> 4;

    float acc[4][4] = {};
    const float* Ap = h + (size_t)(row0 + ar) * Cc + ak;
    const float* Bp = W + (size_t)br * HD + col0 + bc;

    for (int k0 = 0; k0 < Cc; k0 += QBK) {
        float2 av = *reinterpret_cast<const float2*>(Ap + k0);
        As[ak][ar] = av.x;
        As[ak + 1][ar] = av.y;
        float2 bv = *reinterpret_cast<const float2*>(Bp + (size_t)k0 * HD);
        Bs[br][bc] = bv.x;
        Bs[br][bc + 1] = bv.y;
        __syncthreads();
        #pragma unroll
        for (int k = 0; k < QBK; ++k) {
            float a[4], b[4];
            float4 a0 = *reinterpret_cast<const float4*>(&As[k][ty * 4]);
            a[0]=a0.x; a[1]=a0.y; a[2]=a0.z; a[3]=a0.w;
            float4 b0 = *reinterpret_cast<const float4*>(&Bs[k][tx * 4]);
            b[0]=b0.x; b[1]=b0.y; b[2]=b0.z; b[3]=b0.w;
            #pragma unroll
            for (int i = 0; i < 4; ++i)
                #pragma unroll
                for (int j = 0; j < 4; ++j)
                    acc[i][j] += a[i] * b[j];
        }
        __syncthreads();
    }
    #pragma unroll
    for (int i = 0; i < 4; ++i) {
        size_t m = (size_t)(row0 + ty * 4 + i);
        *reinterpret_cast<float4*>(O + m * HD + col0 + tx * 4) =
            make_float4(acc[i][0], acc[i][1], acc[i][2], acc[i][3]);
    }
}

// ===========================================================================
// K2: fp16 HMMA GEMM (e @ We) + fused Q*K/8 epilogue + per-head rowsums
//     CTA: 128 rows x 256 cols, K=512 in 16 chunks of 32.  512 threads.
//     (R5 proven configuration)
// ===========================================================================
#define KC 32
#define NCHUNK 16
#define RSTRIDE 80               // 64B data + 16B pad (conflict-free ldmatrix)
#define A_OFF 0                  // 128 x 80 = 10240
#define B_OFF 10240              // 256 x 80 = 20480
#define BUF_STRIDE 30720
#define SMEM_PE (2*BUF_STRIDE)   // 60 KB

__global__ void __launch_bounds__(512, 1) pe_mma_kernel(
    const float* __restrict__ e, float* __restrict__ eout)
{
    extern __shared__ char smem[];
    const uint32_t sb = smem_u32(smem);
    const int tid  = threadIdx.x;
    const int lane = tid & 31;
    const int w    = tid >> 5;        // 0..15
    const int wm   = w & 3;
    const int wn   = w >> 2;
    const int n0   = blockIdx.x;      // 0..1 (256-col half)
    const int m0   = blockIdx.y * 128;

    // A staging: row = tid>>2 (0..127), quarter = tid&3 (8 floats each)
    const int arow = tid >> 2;
    const int aq   = tid & 3;
    const uint32_t a_sts = (uint32_t)(arow * RSTRIDE + aq * 16);
    const float* eA = e + (size_t)(m0 + arow) * Cc + aq * 8;

    // B staging: row = tid>>1 (0..255), half = tid&1 (16 fp16 each)
    const int brow = tid >> 1;
    const int bh   = tid & 1;
    const uint32_t b_sts = (uint32_t)(brow * RSTRIDE + bh * 32);
    const __half* WhA = g_WeT_h + (size_t)(n0 * 256 + brow) * Cc + bh * 16;

    float acc[2][8][4];
    #pragma unroll
    for (int mt = 0; mt < 2; ++mt)
        #pragma unroll
        for (int nt = 0; nt < 8; ++nt)
            #pragma unroll
            for (int i = 0; i < 4; ++i) acc[mt][nt][i] = 0.f;

    float4 a_reg[2];

    // ---- prologue: stage chunk 0 into buf 0 ----
    {
        cp_async16(sb + B_OFF + b_sts +  0, WhA);
        cp_async16(sb + B_OFF + b_sts + 16, WhA + 8);
        CP_COMMIT();
        a_reg[0] = *reinterpret_cast<const float4*>(eA);
        a_reg[1] = *reinterpret_cast<const float4*>(eA + 4);
        uint4 hv;
        hv.x = pack_h2(a_reg[0].x, a_reg[0].y);
        hv.y = pack_h2(a_reg[0].z, a_reg[0].w);
        hv.z = pack_h2(a_reg[1].x, a_reg[1].y);
        hv.w = pack_h2(a_reg[1].z, a_reg[1].w);
        *reinterpret_cast<uint4*>(smem + A_OFF + a_sts) = hv;
        CP_WAIT0();
        __syncthreads();
    }

    // ---- main loop ----
    for (int s = 0; s < NCHUNK; ++s) {
        const uint32_t buf = (uint32_t)(s & 1) * BUF_STRIDE;
        const uint32_t nb  = (uint32_t)((s + 1) & 1) * BUF_STRIDE;
        const bool more = (s + 1 < NCHUNK);

        if (more) {
            const int k0 = (s + 1) * KC;
            cp_async16(sb + nb + B_OFF + b_sts +  0, WhA + k0);
            cp_async16(sb + nb + B_OFF + b_sts + 16, WhA + k0 + 8);
            CP_COMMIT();
            a_reg[0] = *reinterpret_cast<const float4*>(eA + k0);
            a_reg[1] = *reinterpret_cast<const float4*>(eA + k0 + 4);
        }

        // compute chunk s
        #pragma unroll
        for (int kk = 0; kk < 2; ++kk) {
            const uint32_t kb = (uint32_t)(kk * 32 + (lane >> 4) * 16);
            uint32_t af[2][4];
            #pragma unroll
            for (int mt = 0; mt < 2; ++mt) {
                const uint32_t ra = sb + buf + A_OFF +
                    (uint32_t)((wm*32 + mt*16 + (lane & 15)) * RSTRIDE) + kb;
                ldsm_x4(ra, af[mt][0], af[mt][1], af[mt][2], af[mt][3]);
            }
            uint32_t bf[4][4];
            #pragma unroll
            for (int g = 0; g < 4; ++g) {
                const uint32_t rb = sb + buf + B_OFF +
                    (uint32_t)((wn*64 + g*16 + (lane & 15)) * RSTRIDE) + kb;
                ldsm_x4(rb, bf[g][0], bf[g][1], bf[g][2], bf[g][3]);
            }
            #pragma unroll
            for (int mt = 0; mt < 2; ++mt)
                #pragma unroll
                for (int nt = 0; nt < 8; ++nt) {
                    const int g = nt >> 1, o = nt & 1;
                    mma_f16(acc[mt][nt], af[mt], bf[g][o], bf[g][o+2]);
                }
        }

        if (more) {
            uint4 hv;
            hv.x = pack_h2(a_reg[0].x, a_reg[0].y);
            hv.y = pack_h2(a_reg[0].z, a_reg[0].w);
            hv.z = pack_h2(a_reg[1].x, a_reg[1].y);
            hv.w = pack_h2(a_reg[1].z, a_reg[1].w);
            *reinterpret_cast<uint4*>(smem + nb + A_OFF + a_sts) = hv;
            CP_WAIT0();
        }
        __syncthreads();
    }

    // ---- epilogue: v = acc * (Q*0.125) * K -> e_out; per-head rowsum -> g_s
    const int q  = lane & 3;
    const int rr = lane >> 2;
    const int bi = blockIdx.y >> 1;             // b*N + i
    const int b  = bi >> 8;
    const int jbase = (blockIdx.y & 1) * 128;
    const int cb = n0 * 256 + wn * 64;
    const int head = cb >> 6;

    float2 qv[8];
    #pragma unroll
    for (int nt = 0; nt < 8; ++nt) {
        float2 t = *reinterpret_cast<const float2*>(
            g_Q + (size_t)bi * HD + cb + nt*8 + 2*q);
        qv[nt] = make_float2(t.x * 0.125f, t.y * 0.125f);
    }

    #pragma unroll
    for (int mt = 0; mt < 2; ++mt)
        #pragma unroll
        for (int half = 0; half < 2; ++half) {
            const int r = wm*32 + mt*16 + rr + half*8;
            const size_t m = (size_t)m0 + r;
            const int j = jbase + r;
            const float* kp = g_K + ((size_t)(b * Nn + j)) * HD + cb + 2*q;
            float* op = eout + m * HD + cb + 2*q;
            float hs = 0.f;
            #pragma unroll
            for (int nt = 0; nt < 8; ++nt) {
                float2 kv = *reinterpret_cast<const float2*>(kp + nt*8);
                float v0 = acc[mt][nt][half*2+0] * qv[nt].x * kv.x;
                float v1 = acc[mt][nt][half*2+1] * qv[nt].y * kv.y;
                *reinterpret_cast<float2*>(op + nt*8) = make_float2(v0, v1);
                hs += v0 + v1;
            }
            hs += __shfl_xor_sync(0xffffffffu, hs, 1);
            hs += __shfl_xor_sync(0xffffffffu, hs, 2);
            if (q == 0)
                g_s[m * Hh + head] = fminf(fmaxf(hs, -5.f), 5.f);
        }
}

// ===========================================================================
// K4: softmax over key axis j — one block per (b, i), all 8 heads
// ===========================================================================
__global__ void softmax_kernel()
{
    const int bi = blockIdx.x;       // 0 .. B*N-1
    const int j  = threadIdx.x;      // 0..255

    __shared__ float red[Hh][Nn];

    const float* sp = g_s + ((size_t)bi * Nn + j) * Hh;
    float4 v0 = *reinterpret_cast<const float4*>(sp);
    float4 v1 = *reinterpret_cast<const float4*>(sp + 4);
    float ev[8];
    ev[0] = __expf(v0.x); ev[1] = __expf(v0.y);
    ev[2] = __expf(v0.z); ev[3] = __expf(v0.w);
    ev[4] = __expf(v1.x); ev[5] = __expf(v1.y);
    ev[6] = __expf(v1.z); ev[7] = __expf(v1.w);
    #pragma unroll
    for (int hh = 0; hh < 8; ++hh) red[hh][j] = ev[hh];
    __syncthreads();

    #pragma unroll
    for (int lg = 7; lg >= 0; --lg) {
        const int st = 1 << lg;
        for (int idx = threadIdx.x; idx < 8 * st; idx += Nn) {
            const int hh = idx >> lg;
            const int jj = idx & (st - 1);
            red[hh][jj] += red[hh][jj + st];
        }
        __syncthreads();
    }

    float* wp = g_w + ((size_t)bi * Nn + j) * Hh;
    float o[8];
    #pragma unroll
    for (int hh = 0; hh < 8; ++hh) o[hh] = __fdividef(ev[hh], red[hh][0]);
    *reinterpret_cast<float4*>(wp)     = make_float4(o[0], o[1], o[2], o[3]);
    *reinterpret_cast<float4*>(wp + 4) = make_float4(o[4], o[5], o[6], o[7]);
}

// ===========================================================================
// K5: h_out = softmax weights @ V
// ===========================================================================
__global__ void attn_out_kernel(float* __restrict__ hout)
{
    const int bi = blockIdx.x;
    const int c  = threadIdx.x;
    const int hh = c >> 6;

    __shared__ float ws[Nn * Hh];
    for (int idx = threadIdx.x; idx < Nn * Hh; idx += blockDim.x)
        ws[idx] = g_w[(size_t)bi * Nn * Hh + idx];
    __syncthreads();

    const int b = bi >> 8;
    const float* vb = g_V + (size_t)(b * Nn) * HD + c;
    float a0 = 0.f, a1 = 0.f, a2 = 0.f, a3 = 0.f;
    #pragma unroll 4
    for (int j = 0; j < Nn; j += 4) {
        a0 = fmaf(ws[(j+0) * Hh + hh], vb[(size_t)(j+0) * HD], a0);
        a1 = fmaf(ws[(j+1) * Hh + hh], vb[(size_t)(j+1) * HD], a1);
        a2 = fmaf(ws[(j+2) * Hh + hh], vb[(size_t)(j+2) * HD], a2);
        a3 = fmaf(ws[(j+3) * Hh + hh], vb[(size_t)(j+3) * HD], a3);
    }
    hout[(size_t)bi * HD + c] = (a0 + a1) + (a2 + a3);
}

// ===========================================================================
extern "C" void kernel_launch(void* const* d_in, const int* in_sizes, int n_in,
                              void* d_out, int out_size)
{
    const float* h  = (const float*)d_in[0];
    const float* e  = (const float*)d_in[1];
    const float* Wq = (const float*)d_in[2];
    const float* Wk = (const float*)d_in[3];
    const float* Wv = (const float*)d_in[4];
    const float* We = (const float*)d_in[5];

    float* out  = (float*)d_out;
    float* hout = out;
    float* eout = out + HOUT_ELEMS;

    cudaFuncSetAttribute(pe_mma_kernel,
                         cudaFuncAttributeMaxDynamicSharedMemorySize, SMEM_PE);

    prep_we_kernel<<<HD, Cc>>>(We);
    {
        dim3 grid(HD / QBN, (Bb * Nn) / QBM, 3);
        qkv_kernel<<<grid, 256>>>(h, Wq, Wk, Wv);
    }
    {
        dim3 grid(2, ME_ROWS / 128);
        pe_mma_kernel<<<grid, 512, SMEM_PE>>>(e, eout);
    }
    softmax_kernel<<<Bb * Nn, Nn>>>();
    attn_out_kernel<<<Bb * Nn, HD>>>(hout);
}

// round 9
// speedup vs baseline: 1.1399x; 1.0040x over previous
#include <cuda_runtime.h>
#include <cuda_fp16.h>
#include <cstdint>

// ---------------------------------------------------------------------------
//   h  [B, N, C]  B=4, N=256, C=512;  e [B, N, N, C];  W* [C, 512]
// Outputs packed in d_out: h_out [B,N,512] then e_out [B,N,N,512]
// ---------------------------------------------------------------------------
#define Bb   4
#define Nn   256
#define Cc   512
#define Hh   8
#define HD   512
#define ME_ROWS  (Bb*Nn*Nn)
#define HOUT_ELEMS (Bb*Nn*HD)

__device__ float g_Q[Bb*Nn*HD];
__device__ float g_K[Bb*Nn*HD];
__device__ float g_V[Bb*Nn*HD];
__device__ float g_s[Bb*Nn*Nn*Hh];
__device__ __half g_WeT_h[HD*Cc];   // [n][k] = fp16(We[k][n])

// ===========================================================================
__device__ __forceinline__ uint32_t smem_u32(const void* p) {
    uint32_t a;
    asm("{ .reg .u64 t; cvta.to.shared.u64 t, %1; cvt.u32.u64 %0, t; }" : "=r"(a) : "l"(p));
    return a;
}
__device__ __forceinline__ void cp_async16(uint32_t dst, const void* src) {
    asm volatile("cp.async.cg.shared.global [%0], [%1], 16;" :: "r"(dst), "l"(src));
}
#define CP_COMMIT() asm volatile("cp.async.commit_group;" ::: "memory")
#define CP_WAIT0()  asm volatile("cp.async.wait_group 0;" ::: "memory")

__device__ __forceinline__ void ldsm_x4(uint32_t addr, uint32_t& r0, uint32_t& r1,
                                        uint32_t& r2, uint32_t& r3) {
    asm volatile("ldmatrix.sync.aligned.m8n8.x4.shared.b16 {%0,%1,%2,%3}, [%4];"
        : "=r"(r0), "=r"(r1), "=r"(r2), "=r"(r3) : "r"(addr));
}
__device__ __forceinline__ void mma_f16(float* d, const uint32_t* a,
                                        uint32_t b0, uint32_t b1) {
    asm volatile("mma.sync.aligned.m16n8k16.row.col.f32.f16.f16.f32 "
        "{%0,%1,%2,%3}, {%4,%5,%6,%7}, {%8,%9}, {%0,%1,%2,%3};"
        : "+f"(d[0]), "+f"(d[1]), "+f"(d[2]), "+f"(d[3])
        : "r"(a[0]), "r"(a[1]), "r"(a[2]), "r"(a[3]), "r"(b0), "r"(b1));
}
__device__ __forceinline__ uint32_t pack_h2(float a, float b) {
    __half2 h = __floats2half2_rn(a, b);
    return *reinterpret_cast<uint32_t*>(&h);
}

// ===========================================================================
// K0: We -> WeT fp16 (transposed)
// ===========================================================================
__global__ void prep_we_kernel(const float* __restrict__ We) {
    const int n = blockIdx.x;
    const int k = threadIdx.x;
    g_WeT_h[(size_t)n * Cc + k] = __float2half_rn(We[(size_t)k * HD + n]);
}

// ===========================================================================
// K1: QKV projection — 64x64 tiles, 384 CTAs (fp32 exact)
// ===========================================================================
#define QBM 64
#define QBN 64
#define QBK 8
#define QPAD 68
__global__ void qkv_kernel(const float* __restrict__ h,
                           const float* __restrict__ Wq,
                           const float* __restrict__ Wk,
                           const float* __restrict__ Wv)
{
    __shared__ float As[QBK][QPAD];
    __shared__ float Bs[QBK][QPAD];
    const int z = blockIdx.z;
    const float* W = (z == 0) ? Wq : (z == 1) ? Wk : Wv;
    float* O = (z == 0) ? g_Q : (z == 1) ? g_K : g_V;

    const int row0 = blockIdx.y * QBM;
    const int col0 = blockIdx.x * QBN;
    const int tid  = threadIdx.x;

    const int ar = tid >> 2;              // 0..63
    const int ak = (tid & 3) * 2;         // 0,2,4,6
    const int br = tid >> 5;              // 0..7
    const int bc = (tid & 31) * 2;        // 0..62
    const int tx = tid & 15;
    const int ty = tid >> 4;

    float acc[4][4] = {};
    const float* Ap = h + (size_t)(row0 + ar) * Cc + ak;
    const float* Bp = W + (size_t)br * HD + col0 + bc;

    for (int k0 = 0; k0 < Cc; k0 += QBK) {
        float2 av = *reinterpret_cast<const float2*>(Ap + k0);
        As[ak][ar] = av.x;
        As[ak + 1][ar] = av.y;
        float2 bv = *reinterpret_cast<const float2*>(Bp + (size_t)k0 * HD);
        Bs[br][bc] = bv.x;
        Bs[br][bc + 1] = bv.y;
        __syncthreads();
        #pragma unroll
        for (int k = 0; k < QBK; ++k) {
            float a[4], b[4];
            float4 a0 = *reinterpret_cast<const float4*>(&As[k][ty * 4]);
            a[0]=a0.x; a[1]=a0.y; a[2]=a0.z; a[3]=a0.w;
            float4 b0 = *reinterpret_cast<const float4*>(&Bs[k][tx * 4]);
            b[0]=b0.x; b[1]=b0.y; b[2]=b0.z; b[3]=b0.w;
            #pragma unroll
            for (int i = 0; i < 4; ++i)
                #pragma unroll
                for (int j = 0; j < 4; ++j)
                    acc[i][j] += a[i] * b[j];
        }
        __syncthreads();
    }
    #pragma unroll
    for (int i = 0; i < 4; ++i) {
        size_t m = (size_t)(row0 + ty * 4 + i);
        *reinterpret_cast<float4*>(O + m * HD + col0 + tx * 4) =
            make_float4(acc[i][0], acc[i][1], acc[i][2], acc[i][3]);
    }
}

// ===========================================================================
// K2: fp16 HMMA GEMM (e @ We) + fused Q*K/8 epilogue + per-head rowsums
//     CTA: 128 rows x 256 cols, K=512 in 16 chunks of 32.  512 threads.
//     (R5/R8 proven configuration — at the legacy-HMMA pipe floor)
// ===========================================================================
#define KC 32
#define NCHUNK 16
#define RSTRIDE 80               // 64B data + 16B pad (conflict-free ldmatrix)
#define A_OFF 0                  // 128 x 80 = 10240
#define B_OFF 10240              // 256 x 80 = 20480
#define BUF_STRIDE 30720
#define SMEM_PE (2*BUF_STRIDE)   // 60 KB

__global__ void __launch_bounds__(512, 1) pe_mma_kernel(
    const float* __restrict__ e, float* __restrict__ eout)
{
    extern __shared__ char smem[];
    const uint32_t sb = smem_u32(smem);
    const int tid  = threadIdx.x;
    const int lane = tid & 31;
    const int w    = tid >> 5;        // 0..15
    const int wm   = w & 3;
    const int wn   = w >> 2;
    const int n0   = blockIdx.x;      // 0..1 (256-col half)
    const int m0   = blockIdx.y * 128;

    // A staging: row = tid>>2 (0..127), quarter = tid&3 (8 floats each)
    const int arow = tid >> 2;
    const int aq   = tid & 3;
    const uint32_t a_sts = (uint32_t)(arow * RSTRIDE + aq * 16);
    const float* eA = e + (size_t)(m0 + arow) * Cc + aq * 8;

    // B staging: row = tid>>1 (0..255), half = tid&1 (16 fp16 each)
    const int brow = tid >> 1;
    const int bh   = tid & 1;
    const uint32_t b_sts = (uint32_t)(brow * RSTRIDE + bh * 32);
    const __half* WhA = g_WeT_h + (size_t)(n0 * 256 + brow) * Cc + bh * 16;

    float acc[2][8][4];
    #pragma unroll
    for (int mt = 0; mt < 2; ++mt)
        #pragma unroll
        for (int nt = 0; nt < 8; ++nt)
            #pragma unroll
            for (int i = 0; i < 4; ++i) acc[mt][nt][i] = 0.f;

    float4 a_reg[2];

    // ---- prologue: stage chunk 0 into buf 0 ----
    {
        cp_async16(sb + B_OFF + b_sts +  0, WhA);
        cp_async16(sb + B_OFF + b_sts + 16, WhA + 8);
        CP_COMMIT();
        a_reg[0] = *reinterpret_cast<const float4*>(eA);
        a_reg[1] = *reinterpret_cast<const float4*>(eA + 4);
        uint4 hv;
        hv.x = pack_h2(a_reg[0].x, a_reg[0].y);
        hv.y = pack_h2(a_reg[0].z, a_reg[0].w);
        hv.z = pack_h2(a_reg[1].x, a_reg[1].y);
        hv.w = pack_h2(a_reg[1].z, a_reg[1].w);
        *reinterpret_cast<uint4*>(smem + A_OFF + a_sts) = hv;
        CP_WAIT0();
        __syncthreads();
    }

    // ---- main loop ----
    for (int s = 0; s < NCHUNK; ++s) {
        const uint32_t buf = (uint32_t)(s & 1) * BUF_STRIDE;
        const uint32_t nb  = (uint32_t)((s + 1) & 1) * BUF_STRIDE;
        const bool more = (s + 1 < NCHUNK);

        if (more) {
            const int k0 = (s + 1) * KC;
            cp_async16(sb + nb + B_OFF + b_sts +  0, WhA + k0);
            cp_async16(sb + nb + B_OFF + b_sts + 16, WhA + k0 + 8);
            CP_COMMIT();
            a_reg[0] = *reinterpret_cast<const float4*>(eA + k0);
            a_reg[1] = *reinterpret_cast<const float4*>(eA + k0 + 4);
        }

        // compute chunk s
        #pragma unroll
        for (int kk = 0; kk < 2; ++kk) {
            const uint32_t kb = (uint32_t)(kk * 32 + (lane >> 4) * 16);
            uint32_t af[2][4];
            #pragma unroll
            for (int mt = 0; mt < 2; ++mt) {
                const uint32_t ra = sb + buf + A_OFF +
                    (uint32_t)((wm*32 + mt*16 + (lane & 15)) * RSTRIDE) + kb;
                ldsm_x4(ra, af[mt][0], af[mt][1], af[mt][2], af[mt][3]);
            }
            uint32_t bf[4][4];
            #pragma unroll
            for (int g = 0; g < 4; ++g) {
                const uint32_t rb = sb + buf + B_OFF +
                    (uint32_t)((wn*64 + g*16 + (lane & 15)) * RSTRIDE) + kb;
                ldsm_x4(rb, bf[g][0], bf[g][1], bf[g][2], bf[g][3]);
            }
            #pragma unroll
            for (int mt = 0; mt < 2; ++mt)
                #pragma unroll
                for (int nt = 0; nt < 8; ++nt) {
                    const int g = nt >> 1, o = nt & 1;
                    mma_f16(acc[mt][nt], af[mt], bf[g][o], bf[g][o+2]);
                }
        }

        if (more) {
            uint4 hv;
            hv.x = pack_h2(a_reg[0].x, a_reg[0].y);
            hv.y = pack_h2(a_reg[0].z, a_reg[0].w);
            hv.z = pack_h2(a_reg[1].x, a_reg[1].y);
            hv.w = pack_h2(a_reg[1].z, a_reg[1].w);
            *reinterpret_cast<uint4*>(smem + nb + A_OFF + a_sts) = hv;
            CP_WAIT0();
        }
        __syncthreads();
    }

    // ---- epilogue: v = acc * (Q*0.125) * K -> e_out; per-head rowsum -> g_s
    const int q  = lane & 3;
    const int rr = lane >> 2;
    const int bi = blockIdx.y >> 1;             // b*N + i
    const int b  = bi >> 8;
    const int jbase = (blockIdx.y & 1) * 128;
    const int cb = n0 * 256 + wn * 64;
    const int head = cb >> 6;

    float2 qv[8];
    #pragma unroll
    for (int nt = 0; nt < 8; ++nt) {
        float2 t = *reinterpret_cast<const float2*>(
            g_Q + (size_t)bi * HD + cb + nt*8 + 2*q);
        qv[nt] = make_float2(t.x * 0.125f, t.y * 0.125f);
    }

    #pragma unroll
    for (int mt = 0; mt < 2; ++mt)
        #pragma unroll
        for (int half = 0; half < 2; ++half) {
            const int r = wm*32 + mt*16 + rr + half*8;
            const size_t m = (size_t)m0 + r;
            const int j = jbase + r;
            const float* kp = g_K + ((size_t)(b * Nn + j)) * HD + cb + 2*q;
            float* op = eout + m * HD + cb + 2*q;
            float hs = 0.f;
            #pragma unroll
            for (int nt = 0; nt < 8; ++nt) {
                float2 kv = *reinterpret_cast<const float2*>(kp + nt*8);
                float v0 = acc[mt][nt][half*2+0] * qv[nt].x * kv.x;
                float v1 = acc[mt][nt][half*2+1] * qv[nt].y * kv.y;
                *reinterpret_cast<float2*>(op + nt*8) = make_float2(v0, v1);
                hs += v0 + v1;
            }
            hs += __shfl_xor_sync(0xffffffffu, hs, 1);
            hs += __shfl_xor_sync(0xffffffffu, hs, 2);
            if (q == 0)
                g_s[m * Hh + head] = fminf(fmaxf(hs, -5.f), 5.f);
        }
}

// ===========================================================================
// K3: fused softmax + weighted-V.  One block per (b, 8 i's).  512 threads.
//   Phase 1: exp(g_s) -> smem fp16 ws[h][j][i] (unnormalized) + sums[i][h]
//   Phase 2: thread c: acc[i] += ws[h][j][i] * V[b,j,c]; divide by sum at end
// ===========================================================================
#define WPAD 2056    // halfs per head region: 256*8 + 8 (16B aligned, bank-skewed)

__global__ void __launch_bounds__(512) softmax_attn_kernel(float* __restrict__ hout)
{
    __shared__ __half ws[Hh * WPAD];   // ~32.9 KB
    __shared__ float sums[64];         // [i][h]

    const int b   = blockIdx.y;
    const int i0  = blockIdx.x * 8;
    const int tid = threadIdx.x;

    // ---- phase 1: exponentials + per-(i,h) sums ----
    {
        const int team = tid >> 3;     // 0..63  = ii*8 + hh
        const int ii   = team >> 3;
        const int hh   = team & 7;
        const int sub  = tid & 7;      // j-chunk of 32
        const float* sp = g_s +
            ((size_t)((b * Nn + i0 + ii) * Nn) + sub * 32) * Hh + hh;
        __half* wp = ws + hh * WPAD + (sub * 32) * 8 + ii;
        float s = 0.f;
        #pragma unroll
        for (int jj = 0; jj < 32; ++jj) {
            float ev = __expf(sp[jj * Hh]);
            s += ev;
            wp[jj * 8] = __float2half(ev);
        }
        s += __shfl_down_sync(0xffffffffu, s, 4, 8);
        s += __shfl_down_sync(0xffffffffu, s, 2, 8);
        s += __shfl_down_sync(0xffffffffu, s, 1, 8);
        if (sub == 0) sums[ii * 8 + hh] = s;
    }
    __syncthreads();

    // ---- phase 2: acc[i] = sum_j w[j][i] * V[b,j,c] ----
    const int hh = tid >> 6;
    const float* vb = g_V + ((size_t)b * Nn) * HD + tid;
    const __half* wrow = ws + hh * WPAD;

    float acc[8] = {};
    #pragma unroll 4
    for (int j = 0; j < Nn; ++j) {
        const float v = vb[(size_t)j * HD];
        uint4 wv = *reinterpret_cast<const uint4*>(wrow + j * 8);
        float2 f01 = __half22float2(*reinterpret_cast<__half2*>(&wv.x));
        float2 f23 = __half22float2(*reinterpret_cast<__half2*>(&wv.y));
        float2 f45 = __half22float2(*reinterpret_cast<__half2*>(&wv.z));
        float2 f67 = __half22float2(*reinterpret_cast<__half2*>(&wv.w));
        acc[0] = fmaf(f01.x, v, acc[0]);
        acc[1] = fmaf(f01.y, v, acc[1]);
        acc[2] = fmaf(f23.x, v, acc[2]);
        acc[3] = fmaf(f23.y, v, acc[3]);
        acc[4] = fmaf(f45.x, v, acc[4]);
        acc[5] = fmaf(f45.y, v, acc[5]);
        acc[6] = fmaf(f67.x, v, acc[6]);
        acc[7] = fmaf(f67.y, v, acc[7]);
    }

    float* op = hout + ((size_t)(b * Nn + i0)) * HD + tid;
    #pragma unroll
    for (int i = 0; i < 8; ++i)
        op[(size_t)i * HD] = acc[i] * __fdividef(1.f, sums[i * 8 + hh]);
}

// ===========================================================================
extern "C" void kernel_launch(void* const* d_in, const int* in_sizes, int n_in,
                              void* d_out, int out_size)
{
    const float* h  = (const float*)d_in[0];
    const float* e  = (const float*)d_in[1];
    const float* Wq = (const float*)d_in[2];
    const float* Wk = (const float*)d_in[3];
    const float* Wv = (const float*)d_in[4];
    const float* We = (const float*)d_in[5];

    float* out  = (float*)d_out;
    float* hout = out;
    float* eout = out + HOUT_ELEMS;

    cudaFuncSetAttribute(pe_mma_kernel,
                         cudaFuncAttributeMaxDynamicSharedMemorySize, SMEM_PE);

    prep_we_kernel<<<HD, Cc>>>(We);
    {
        dim3 grid(HD / QBN, (Bb * Nn) / QBM, 3);
        qkv_kernel<<<grid, 256>>>(h, Wq, Wk, Wv);
    }
    {
        dim3 grid(2, ME_ROWS / 128);
        pe_mma_kernel<<<grid, 512, SMEM_PE>>>(e, eout);
    }
    {
        dim3 grid(Nn / 8, Bb);
        softmax_attn_kernel<<<grid, 512>>>(hout);
    }
}

// round 10
// speedup vs baseline: 1.1758x; 1.0315x over previous
#include <cuda_runtime.h>
#include <cuda_fp16.h>
#include <cstdint>

// ---------------------------------------------------------------------------
//   h  [B, N, C]  B=4, N=256, C=512;  e [B, N, N, C];  W* [C, 512]
// Outputs packed in d_out: h_out [B,N,512] then e_out [B,N,N,512]
// ---------------------------------------------------------------------------
#define Bb   4
#define Nn   256
#define Cc   512
#define Hh   8
#define HD   512
#define ME_ROWS  (Bb*Nn*Nn)
#define HOUT_ELEMS (Bb*Nn*HD)

__device__ float g_Q[Bb*Nn*HD];
__device__ float g_K[Bb*Nn*HD];
__device__ float g_V[Bb*Nn*HD];
__device__ float g_s[Bb*Nn*Nn*Hh];
__device__ __half g_WeT_h[HD*Cc];   // [n][k] = fp16(We[k][n])

// ===========================================================================
__device__ __forceinline__ uint32_t smem_u32(const void* p) {
    uint32_t a;
    asm("{ .reg .u64 t; cvta.to.shared.u64 t, %1; cvt.u32.u64 %0, t; }" : "=r"(a) : "l"(p));
    return a;
}
__device__ __forceinline__ void cp_async16(uint32_t dst, const void* src) {
    asm volatile("cp.async.cg.shared.global [%0], [%1], 16;" :: "r"(dst), "l"(src));
}
#define CP_COMMIT() asm volatile("cp.async.commit_group;" ::: "memory")
#define CP_WAIT0()  asm volatile("cp.async.wait_group 0;" ::: "memory")

__device__ __forceinline__ void ldsm_x4(uint32_t addr, uint32_t& r0, uint32_t& r1,
                                        uint32_t& r2, uint32_t& r3) {
    asm volatile("ldmatrix.sync.aligned.m8n8.x4.shared.b16 {%0,%1,%2,%3}, [%4];"
        : "=r"(r0), "=r"(r1), "=r"(r2), "=r"(r3) : "r"(addr));
}
__device__ __forceinline__ void mma_f16(float* d, const uint32_t* a,
                                        uint32_t b0, uint32_t b1) {
    asm volatile("mma.sync.aligned.m16n8k16.row.col.f32.f16.f16.f32 "
        "{%0,%1,%2,%3}, {%4,%5,%6,%7}, {%8,%9}, {%0,%1,%2,%3};"
        : "+f"(d[0]), "+f"(d[1]), "+f"(d[2]), "+f"(d[3])
        : "r"(a[0]), "r"(a[1]), "r"(a[2]), "r"(a[3]), "r"(b0), "r"(b1));
}
__device__ __forceinline__ uint32_t pack_h2(float a, float b) {
    __half2 h = __floats2half2_rn(a, b);
    return *reinterpret_cast<uint32_t*>(&h);
}

// ===========================================================================
// K0: We -> WeT fp16 (transposed)
// ===========================================================================
__global__ void prep_we_kernel(const float* __restrict__ We) {
    const int n = blockIdx.x;
    const int k = threadIdx.x;
    g_WeT_h[(size_t)n * Cc + k] = __float2half_rn(We[(size_t)k * HD + n]);
}

// ===========================================================================
// K1: QKV projection — 64x64 tiles, 384 CTAs (fp32 exact)
// ===========================================================================
#define QBM 64
#define QBN 64
#define QBK 8
#define QPAD 68
__global__ void qkv_kernel(const float* __restrict__ h,
                           const float* __restrict__ Wq,
                           const float* __restrict__ Wk,
                           const float* __restrict__ Wv)
{
    __shared__ float As[QBK][QPAD];
    __shared__ float Bs[QBK][QPAD];
    const int z = blockIdx.z;
    const float* W = (z == 0) ? Wq : (z == 1) ? Wk : Wv;
    float* O = (z == 0) ? g_Q : (z == 1) ? g_K : g_V;

    const int row0 = blockIdx.y * QBM;
    const int col0 = blockIdx.x * QBN;
    const int tid  = threadIdx.x;

    const int ar = tid >> 2;              // 0..63
    const int ak = (tid & 3) * 2;         // 0,2,4,6
    const int br = tid >> 5;              // 0..7
    const int bc = (tid & 31) * 2;        // 0..62
    const int tx = tid & 15;
    const int ty = tid >> 4;

    float acc[4][4] = {};
    const float* Ap = h + (size_t)(row0 + ar) * Cc + ak;
    const float* Bp = W + (size_t)br * HD + col0 + bc;

    for (int k0 = 0; k0 < Cc; k0 += QBK) {
        float2 av = *reinterpret_cast<const float2*>(Ap + k0);
        As[ak][ar] = av.x;
        As[ak + 1][ar] = av.y;
        float2 bv = *reinterpret_cast<const float2*>(Bp + (size_t)k0 * HD);
        Bs[br][bc] = bv.x;
        Bs[br][bc + 1] = bv.y;
        __syncthreads();
        #pragma unroll
        for (int k = 0; k < QBK; ++k) {
            float a[4], b[4];
            float4 a0 = *reinterpret_cast<const float4*>(&As[k][ty * 4]);
            a[0]=a0.x; a[1]=a0.y; a[2]=a0.z; a[3]=a0.w;
            float4 b0 = *reinterpret_cast<const float4*>(&Bs[k][tx * 4]);
            b[0]=b0.x; b[1]=b0.y; b[2]=b0.z; b[3]=b0.w;
            #pragma unroll
            for (int i = 0; i < 4; ++i)
                #pragma unroll
                for (int j = 0; j < 4; ++j)
                    acc[i][j] += a[i] * b[j];
        }
        __syncthreads();
    }
    #pragma unroll
    for (int i = 0; i < 4; ++i) {
        size_t m = (size_t)(row0 + ty * 4 + i);
        *reinterpret_cast<float4*>(O + m * HD + col0 + tx * 4) =
            make_float4(acc[i][0], acc[i][1], acc[i][2], acc[i][3]);
    }
}

// ===========================================================================
// K2: fp16 HMMA GEMM (e @ We) + fused Q*K/8 epilogue + per-head rowsums
//     CTA: 128 rows x 256 cols, K=512 in 16 chunks of 32.  512 threads.
//     (R5/R8 proven configuration)
// ===========================================================================
#define KC 32
#define NCHUNK 16
#define RSTRIDE 80               // 64B data + 16B pad (conflict-free ldmatrix)
#define A_OFF 0                  // 128 x 80 = 10240
#define B_OFF 10240              // 256 x 80 = 20480
#define BUF_STRIDE 30720
#define SMEM_PE (2*BUF_STRIDE)   // 60 KB

__global__ void __launch_bounds__(512, 1) pe_mma_kernel(
    const float* __restrict__ e, float* __restrict__ eout)
{
    extern __shared__ char smem[];
    const uint32_t sb = smem_u32(smem);
    const int tid  = threadIdx.x;
    const int lane = tid & 31;
    const int w    = tid >> 5;        // 0..15
    const int wm   = w & 3;
    const int wn   = w >> 2;
    const int n0   = blockIdx.x;      // 0..1 (256-col half)
    const int m0   = blockIdx.y * 128;

    // A staging: row = tid>>2 (0..127), quarter = tid&3 (8 floats each)
    const int arow = tid >> 2;
    const int aq   = tid & 3;
    const uint32_t a_sts = (uint32_t)(arow * RSTRIDE + aq * 16);
    const float* eA = e + (size_t)(m0 + arow) * Cc + aq * 8;

    // B staging: row = tid>>1 (0..255), half = tid&1 (16 fp16 each)
    const int brow = tid >> 1;
    const int bh   = tid & 1;
    const uint32_t b_sts = (uint32_t)(brow * RSTRIDE + bh * 32);
    const __half* WhA = g_WeT_h + (size_t)(n0 * 256 + brow) * Cc + bh * 16;

    float acc[2][8][4];
    #pragma unroll
    for (int mt = 0; mt < 2; ++mt)
        #pragma unroll
        for (int nt = 0; nt < 8; ++nt)
            #pragma unroll
            for (int i = 0; i < 4; ++i) acc[mt][nt][i] = 0.f;

    float4 a_reg[2];

    // ---- prologue: stage chunk 0 into buf 0 ----
    {
        cp_async16(sb + B_OFF + b_sts +  0, WhA);
        cp_async16(sb + B_OFF + b_sts + 16, WhA + 8);
        CP_COMMIT();
        a_reg[0] = *reinterpret_cast<const float4*>(eA);
        a_reg[1] = *reinterpret_cast<const float4*>(eA + 4);
        uint4 hv;
        hv.x = pack_h2(a_reg[0].x, a_reg[0].y);
        hv.y = pack_h2(a_reg[0].z, a_reg[0].w);
        hv.z = pack_h2(a_reg[1].x, a_reg[1].y);
        hv.w = pack_h2(a_reg[1].z, a_reg[1].w);
        *reinterpret_cast<uint4*>(smem + A_OFF + a_sts) = hv;
        CP_WAIT0();
        __syncthreads();
    }

    // ---- main loop ----
    for (int s = 0; s < NCHUNK; ++s) {
        const uint32_t buf = (uint32_t)(s & 1) * BUF_STRIDE;
        const uint32_t nb  = (uint32_t)((s + 1) & 1) * BUF_STRIDE;
        const bool more = (s + 1 < NCHUNK);

        if (more) {
            const int k0 = (s + 1) * KC;
            cp_async16(sb + nb + B_OFF + b_sts +  0, WhA + k0);
            cp_async16(sb + nb + B_OFF + b_sts + 16, WhA + k0 + 8);
            CP_COMMIT();
            a_reg[0] = *reinterpret_cast<const float4*>(eA + k0);
            a_reg[1] = *reinterpret_cast<const float4*>(eA + k0 + 4);
        }

        // compute chunk s
        #pragma unroll
        for (int kk = 0; kk < 2; ++kk) {
            const uint32_t kb = (uint32_t)(kk * 32 + (lane >> 4) * 16);
            uint32_t af[2][4];
            #pragma unroll
            for (int mt = 0; mt < 2; ++mt) {
                const uint32_t ra = sb + buf + A_OFF +
                    (uint32_t)((wm*32 + mt*16 + (lane & 15)) * RSTRIDE) + kb;
                ldsm_x4(ra, af[mt][0], af[mt][1], af[mt][2], af[mt][3]);
            }
            uint32_t bf[4][4];
            #pragma unroll
            for (int g = 0; g < 4; ++g) {
                const uint32_t rb = sb + buf + B_OFF +
                    (uint32_t)((wn*64 + g*16 + (lane & 15)) * RSTRIDE) + kb;
                ldsm_x4(rb, bf[g][0], bf[g][1], bf[g][2], bf[g][3]);
            }
            #pragma unroll
            for (int mt = 0; mt < 2; ++mt)
                #pragma unroll
                for (int nt = 0; nt < 8; ++nt) {
                    const int g = nt >> 1, o = nt & 1;
                    mma_f16(acc[mt][nt], af[mt], bf[g][o], bf[g][o+2]);
                }
        }

        if (more) {
            uint4 hv;
            hv.x = pack_h2(a_reg[0].x, a_reg[0].y);
            hv.y = pack_h2(a_reg[0].z, a_reg[0].w);
            hv.z = pack_h2(a_reg[1].x, a_reg[1].y);
            hv.w = pack_h2(a_reg[1].z, a_reg[1].w);
            *reinterpret_cast<uint4*>(smem + nb + A_OFF + a_sts) = hv;
            CP_WAIT0();
        }
        __syncthreads();
    }

    // ---- epilogue: v = acc * (Q*0.125) * K -> e_out; per-head rowsum -> g_s
    const int q  = lane & 3;
    const int rr = lane >> 2;
    const int bi = blockIdx.y >> 1;             // b*N + i
    const int b  = bi >> 8;
    const int jbase = (blockIdx.y & 1) * 128;
    const int cb = n0 * 256 + wn * 64;
    const int head = cb >> 6;

    float2 qv[8];
    #pragma unroll
    for (int nt = 0; nt < 8; ++nt) {
        float2 t = *reinterpret_cast<const float2*>(
            g_Q + (size_t)bi * HD + cb + nt*8 + 2*q);
        qv[nt] = make_float2(t.x * 0.125f, t.y * 0.125f);
    }

    #pragma unroll
    for (int mt = 0; mt < 2; ++mt)
        #pragma unroll
        for (int half = 0; half < 2; ++half) {
            const int r = wm*32 + mt*16 + rr + half*8;
            const size_t m = (size_t)m0 + r;
            const int j = jbase + r;
            const float* kp = g_K + ((size_t)(b * Nn + j)) * HD + cb + 2*q;
            float* op = eout + m * HD + cb + 2*q;
            float hs = 0.f;
            #pragma unroll
            for (int nt = 0; nt < 8; ++nt) {
                float2 kv = *reinterpret_cast<const float2*>(kp + nt*8);
                float v0 = acc[mt][nt][half*2+0] * qv[nt].x * kv.x;
                float v1 = acc[mt][nt][half*2+1] * qv[nt].y * kv.y;
                *reinterpret_cast<float2*>(op + nt*8) = make_float2(v0, v1);
                hs += v0 + v1;
            }
            hs += __shfl_xor_sync(0xffffffffu, hs, 1);
            hs += __shfl_xor_sync(0xffffffffu, hs, 2);
            if (q == 0)
                g_s[m * Hh + head] = fminf(fmaxf(hs, -5.f), 5.f);
        }
}

// ===========================================================================
// K3: fused softmax + weighted-V.  One block per (b, 4 i's).  256 blocks,
//     512 threads, 2 blocks/SM.
//   Phase 1: exp(g_s) -> smem fp16 ws[h][j][i] (unnormalized) + sums[i][h]
//   Phase 2: thread c: acc[i] += ws[h][j][i] * V[b,j,c]; divide by sum at end
// ===========================================================================
#define WPAD4 1032   // halfs per head region: 256*4 + 8 (2064 B: 16B-aligned, bank-skewed)

__global__ void __launch_bounds__(512, 2) softmax_attn_kernel(float* __restrict__ hout)
{
    __shared__ __half ws[Hh * WPAD4];  // ~16.5 KB
    __shared__ float sums[32];         // [i][h]

    const int b   = blockIdx.y;
    const int i0  = blockIdx.x * 4;
    const int tid = threadIdx.x;

    // ---- phase 1: exponentials + per-(i,h) sums ----
    {
        const int team = tid >> 4;     // 0..31  = ii*8 + hh
        const int ii   = team >> 3;
        const int hh   = team & 7;
        const int sub  = tid & 15;     // j-chunk of 16
        const float* sp = g_s +
            ((size_t)((b * Nn + i0 + ii) * Nn) + sub * 16) * Hh + hh;
        __half* wp = ws + hh * WPAD4 + (sub * 16) * 4 + ii;
        float s = 0.f;
        #pragma unroll
        for (int jj = 0; jj < 16; ++jj) {
            float ev = __expf(sp[jj * Hh]);
            s += ev;
            wp[jj * 4] = __float2half(ev);
        }
        s += __shfl_down_sync(0xffffffffu, s, 8, 16);
        s += __shfl_down_sync(0xffffffffu, s, 4, 16);
        s += __shfl_down_sync(0xffffffffu, s, 2, 16);
        s += __shfl_down_sync(0xffffffffu, s, 1, 16);
        if (sub == 0) sums[ii * 8 + hh] = s;
    }
    __syncthreads();

    // ---- phase 2: acc[i] = sum_j w[j][i] * V[b,j,c] ----
    const int hh = tid >> 6;
    const float* vb = g_V + ((size_t)b * Nn) * HD + tid;
    const __half* wrow = ws + hh * WPAD4;

    float acc[4] = {};
    #pragma unroll 8
    for (int j = 0; j < Nn; ++j) {
        const float v = vb[(size_t)j * HD];
        uint2 wv = *reinterpret_cast<const uint2*>(wrow + j * 4);
        float2 f01 = __half22float2(*reinterpret_cast<__half2*>(&wv.x));
        float2 f23 = __half22float2(*reinterpret_cast<__half2*>(&wv.y));
        acc[0] = fmaf(f01.x, v, acc[0]);
        acc[1] = fmaf(f01.y, v, acc[1]);
        acc[2] = fmaf(f23.x, v, acc[2]);
        acc[3] = fmaf(f23.y, v, acc[3]);
    }

    float* op = hout + ((size_t)(b * Nn + i0)) * HD + tid;
    #pragma unroll
    for (int i = 0; i < 4; ++i)
        op[(size_t)i * HD] = acc[i] * __fdividef(1.f, sums[i * 8 + hh]);
}

// ===========================================================================
extern "C" void kernel_launch(void* const* d_in, const int* in_sizes, int n_in,
                              void* d_out, int out_size)
{
    const float* h  = (const float*)d_in[0];
    const float* e  = (const float*)d_in[1];
    const float* Wq = (const float*)d_in[2];
    const float* Wk = (const float*)d_in[3];
    const float* Wv = (const float*)d_in[4];
    const float* We = (const float*)d_in[5];

    float* out  = (float*)d_out;
    float* hout = out;
    float* eout = out + HOUT_ELEMS;

    cudaFuncSetAttribute(pe_mma_kernel,
                         cudaFuncAttributeMaxDynamicSharedMemorySize, SMEM_PE);

    prep_we_kernel<<<HD, Cc>>>(We);
    {
        dim3 grid(HD / QBN, (Bb * Nn) / QBM, 3);
        qkv_kernel<<<grid, 256>>>(h, Wq, Wk, Wv);
    }
    {
        dim3 grid(2, ME_ROWS / 128);
        pe_mma_kernel<<<grid, 512, SMEM_PE>>>(e, eout);
    }
    {
        dim3 grid(Nn / 4, Bb);
        softmax_attn_kernel<<<grid, 512>>>(hout);
    }
}